// round 6
// baseline (speedup 1.0000x reference)
#include <cuda_runtime.h>

#define NMAX   50000
#define D      96
#define D4     24    // D/4 float4 per row

// ---------------- scratch (device globals; no allocation allowed) ----------
__device__ float4 g_pool[NMAX * D4];            // pooled neighbor sums (19.2 MB)
__device__ float  g_sum[D];
__device__ float  g_sumsq[D];

// ---------------- K1: zero pool + BN accumulators ---------------------------
__global__ void zero_kernel(int n4) {
    int i = blockIdx.x * blockDim.x + threadIdx.x;
    if (i < D) { g_sum[i] = 0.f; g_sumsq[i] = 0.f; }
    if (i >= n4) return;
    g_pool[i] = make_float4(0.f, 0.f, 0.f, 0.f);
}

// ---------------- K2: edge scatter: pool[dst] += feature[src] ---------------
// 8 threads per edge, 3 float4 chunks per thread (chunks j, j+8, j+16)
__global__ void scatter_kernel(const float4* __restrict__ feat,
                               const int* __restrict__ src,
                               const int* __restrict__ dst, int total) {
    int i = blockIdx.x * blockDim.x + threadIdx.x;
    if (i >= total) return;
    int e = i >> 3;          // edge
    int j = i & 7;           // chunk lane 0..7
    int s = __ldg(src + e);
    int d = __ldg(dst + e);
    const float4* fp = feat + (long)s * D4 + j;
    float4* pp = g_pool + (long)d * D4 + j;
    float4 v0 = __ldg(fp);
    float4 v1 = __ldg(fp + 8);
    float4 v2 = __ldg(fp + 16);
    asm volatile("red.global.add.v4.f32 [%0], {%1,%2,%3,%4};"
                 :: "l"(pp), "f"(v0.x), "f"(v0.y), "f"(v0.z), "f"(v0.w) : "memory");
    asm volatile("red.global.add.v4.f32 [%0], {%1,%2,%3,%4};"
                 :: "l"(pp + 8), "f"(v1.x), "f"(v1.y), "f"(v1.z), "f"(v1.w) : "memory");
    asm volatile("red.global.add.v4.f32 [%0], {%1,%2,%3,%4};"
                 :: "l"(pp + 16), "f"(v2.x), "f"(v2.y), "f"(v2.z), "f"(v2.w) : "memory");
}

// ---------------- K3: fused  h2 = relu((pool+s*feat)@W1+b1)@W2+b2 + stats ---
#define TM 128
#define AS 100   // padded row stride for A tile

__global__ __launch_bounds__(256, 2)
void mlp_kernel(const float4* __restrict__ feat,
                const float* __restrict__ eps,
                const float* __restrict__ W1, const float* __restrict__ b1,
                const float* __restrict__ W2, const float* __restrict__ b2,
                float* __restrict__ out, int n) {
    extern __shared__ float smem[];
    float* As    = smem;                 // TM * AS
    float* Ws    = smem + TM * AS;       // 96*96
    float* s_sum = Ws + D * D;           // 96
    float* s_sq  = s_sum + D;            // 96

    const int tid = threadIdx.x;
    const int tx  = tid & 7;
    const int ty  = tid >> 3;
    const int rb  = blockIdx.x * TM;

    if (tid < D) { s_sum[tid] = 0.f; s_sq[tid] = 0.f; }

    const float se = 1.0f + __ldg(eps);
    for (int i = tid; i < TM * D4; i += 256) {
        int r  = i / D4;
        int c4 = i - r * D4;
        float4 v = make_float4(0.f, 0.f, 0.f, 0.f);
        if (rb + r < n) {
            long idx = (long)(rb + r) * D4 + c4;
            float4 p = g_pool[idx];
            float4 f = __ldg(feat + idx);
            v.x = fmaf(se, f.x, p.x);
            v.y = fmaf(se, f.y, p.y);
            v.z = fmaf(se, f.z, p.z);
            v.w = fmaf(se, f.w, p.w);
        }
        *(float4*)(As + r * AS + c4 * 4) = v;
    }
    for (int i = tid; i < (D * D) / 4; i += 256)
        ((float4*)Ws)[i] = ((const float4*)W1)[i];
    __syncthreads();

    float acc[4][12];
    #pragma unroll
    for (int r = 0; r < 4; r++)
        #pragma unroll
        for (int c = 0; c < 12; c++) acc[r][c] = 0.f;

    // ---- GEMM1 ----
    #pragma unroll 6
    for (int k4 = 0; k4 < D; k4 += 4) {
        float4 av[4];
        #pragma unroll
        for (int r = 0; r < 4; r++)
            av[r] = *(const float4*)(As + (ty * 4 + r) * AS + k4);
        #pragma unroll
        for (int kk = 0; kk < 4; kk++) {
            int k = k4 + kk;
            float4 w0 = *(const float4*)(Ws + k * D + tx * 12);
            float4 w1 = *(const float4*)(Ws + k * D + tx * 12 + 4);
            float4 w2 = *(const float4*)(Ws + k * D + tx * 12 + 8);
            float wv[12] = {w0.x,w0.y,w0.z,w0.w, w1.x,w1.y,w1.z,w1.w,
                            w2.x,w2.y,w2.z,w2.w};
            #pragma unroll
            for (int r = 0; r < 4; r++) {
                float a = (kk == 0) ? av[r].x : (kk == 1) ? av[r].y
                        : (kk == 2) ? av[r].z : av[r].w;
                #pragma unroll
                for (int c = 0; c < 12; c++)
                    acc[r][c] = fmaf(a, wv[c], acc[r][c]);
            }
        }
    }
    __syncthreads();

    #pragma unroll
    for (int c = 0; c < 12; c++) {
        float bb = __ldg(b1 + tx * 12 + c);
        #pragma unroll
        for (int r = 0; r < 4; r++)
            As[(ty * 4 + r) * AS + tx * 12 + c] = fmaxf(acc[r][c] + bb, 0.f);
    }
    for (int i = tid; i < (D * D) / 4; i += 256)
        ((float4*)Ws)[i] = ((const float4*)W2)[i];
    __syncthreads();

    #pragma unroll
    for (int r = 0; r < 4; r++)
        #pragma unroll
        for (int c = 0; c < 12; c++) acc[r][c] = 0.f;

    // ---- GEMM2 ----
    #pragma unroll 6
    for (int k4 = 0; k4 < D; k4 += 4) {
        float4 av[4];
        #pragma unroll
        for (int r = 0; r < 4; r++)
            av[r] = *(const float4*)(As + (ty * 4 + r) * AS + k4);
        #pragma unroll
        for (int kk = 0; kk < 4; kk++) {
            int k = k4 + kk;
            float4 w0 = *(const float4*)(Ws + k * D + tx * 12);
            float4 w1 = *(const float4*)(Ws + k * D + tx * 12 + 4);
            float4 w2 = *(const float4*)(Ws + k * D + tx * 12 + 8);
            float wv[12] = {w0.x,w0.y,w0.z,w0.w, w1.x,w1.y,w1.z,w1.w,
                            w2.x,w2.y,w2.z,w2.w};
            #pragma unroll
            for (int r = 0; r < 4; r++) {
                float a = (kk == 0) ? av[r].x : (kk == 1) ? av[r].y
                        : (kk == 2) ? av[r].z : av[r].w;
                #pragma unroll
                for (int c = 0; c < 12; c++)
                    acc[r][c] = fmaf(a, wv[c], acc[r][c]);
            }
        }
    }

    // ---- epilogue: +b2, store h2, reduce BN sums ----
    #pragma unroll
    for (int c = 0; c < 12; c++) {
        int col = tx * 12 + c;
        float bb = __ldg(b2 + col);
        float s = 0.f, s2 = 0.f;
        #pragma unroll
        for (int r = 0; r < 4; r++) {
            int row = rb + ty * 4 + r;
            float v = acc[r][c] + bb;
            if (row < n) {
                out[row * D + col] = v;
                s  += v;
                s2 += v * v;
            }
        }
        s  += __shfl_xor_sync(0xffffffffu, s, 8);
        s  += __shfl_xor_sync(0xffffffffu, s, 16);
        s2 += __shfl_xor_sync(0xffffffffu, s2, 8);
        s2 += __shfl_xor_sync(0xffffffffu, s2, 16);
        if ((tid & 31) < 8) {
            atomicAdd(&s_sum[col], s);
            atomicAdd(&s_sq[col], s2);
        }
    }
    __syncthreads();
    if (tid < D) {
        atomicAdd(&g_sum[tid],   s_sum[tid]);
        atomicAdd(&g_sumsq[tid], s_sq[tid]);
    }
}

// ---------------- K4: apply BN + ReLU, 2 float4 per thread -------------------
__global__ void apply_kernel(const float* __restrict__ gamma,
                             const float* __restrict__ beta,
                             float invN, float4* __restrict__ out4, int n4) {
    __shared__ __align__(16) float sc[D];
    __shared__ __align__(16) float sh[D];
    int tid = threadIdx.x;
    if (tid < D) {
        float mean = g_sum[tid] * invN;
        float var  = g_sumsq[tid] * invN - mean * mean;
        float rstd = rsqrtf(var + 1e-5f);
        float s    = rstd * gamma[tid];
        sc[tid] = s;
        sh[tid] = beta[tid] - mean * s;
    }
    __syncthreads();

    int base = (blockIdx.x * blockDim.x + tid) * 2;
    #pragma unroll
    for (int u = 0; u < 2; u++) {
        int i = base + u;
        if (i >= n4) return;
        int c4 = i % D4;
        float4 h  = out4[i];
        float4 s4 = ((const float4*)sc)[c4];
        float4 h4 = ((const float4*)sh)[c4];
        h.x = fmaxf(fmaf(h.x, s4.x, h4.x), 0.f);
        h.y = fmaxf(fmaf(h.y, s4.y, h4.y), 0.f);
        h.z = fmaxf(fmaf(h.z, s4.z, h4.z), 0.f);
        h.w = fmaxf(fmaf(h.w, s4.w, h4.w), 0.f);
        out4[i] = h;
    }
}

// ---------------------------------------------------------------------------
extern "C" void kernel_launch(void* const* d_in, const int* in_sizes, int n_in,
                              void* d_out, int out_size) {
    const float* feature = (const float*)d_in[0];
    const int*   src     = (const int*)d_in[1];
    const int*   dst     = (const int*)d_in[2];
    const float* W1      = (const float*)d_in[3];
    const float* b1      = (const float*)d_in[4];
    const float* W2      = (const float*)d_in[5];
    const float* b2      = (const float*)d_in[6];
    const float* gamma   = (const float*)d_in[7];
    const float* beta    = (const float*)d_in[8];
    const float* eps     = (const float*)d_in[9];
    float* out = (float*)d_out;

    const int n  = in_sizes[0] / D;     // 50000
    const int E  = in_sizes[1];         // 800000
    const int n4 = n * D4;

    zero_kernel<<<(n4 + 255) / 256, 256>>>(n4);

    int total = E * 8;                   // 6.4M threads, 3 chunks each
    scatter_kernel<<<(total + 255) / 256, 256>>>((const float4*)feature,
                                                 src, dst, total);

    const int SMEM = (TM * AS + D * D + 2 * D) * (int)sizeof(float); // 88832 B
    cudaFuncSetAttribute(mlp_kernel,
                         cudaFuncAttributeMaxDynamicSharedMemorySize, SMEM);
    mlp_kernel<<<(n + TM - 1) / TM, 256, SMEM>>>((const float4*)feature, eps,
                                                 W1, b1, W2, b2, out, n);

    apply_kernel<<<(n4 / 2 + 255) / 256, 256>>>(gamma, beta, 1.0f / (float)n,
                                                (float4*)out, n4);
}

// round 7
// speedup vs baseline: 1.0141x; 1.0141x over previous
#include <cuda_runtime.h>

#define NMAX   50000
#define D      96
#define D4     24    // D/4 float4 per row

// ---------------- scratch (device globals; no allocation allowed) ----------
__device__ float4 g_pool[NMAX * D4];            // pooled neighbor sums (19.2 MB)
__device__ float  g_sum[D];
__device__ float  g_sumsq[D];

// ---------------- K1: zero pool + BN accumulators ---------------------------
__global__ void zero_kernel(int n4) {
    int i = blockIdx.x * blockDim.x + threadIdx.x;
    if (i < D) { g_sum[i] = 0.f; g_sumsq[i] = 0.f; }
    if (i >= n4) return;
    g_pool[i] = make_float4(0.f, 0.f, 0.f, 0.f);
}

// ---------------- K2: edge scatter: pool[dst] += feature[src] ---------------
// 8 threads per edge, 3 float4 chunks per thread (chunks j, j+8, j+16)
__global__ void scatter_kernel(const float4* __restrict__ feat,
                               const int* __restrict__ src,
                               const int* __restrict__ dst, int total) {
    int i = blockIdx.x * blockDim.x + threadIdx.x;
    if (i >= total) return;
    int e = i >> 3;          // edge
    int j = i & 7;           // chunk lane 0..7
    int s = __ldg(src + e);
    int d = __ldg(dst + e);
    const float4* fp = feat + (long)s * D4 + j;
    float4* pp = g_pool + (long)d * D4 + j;
    float4 v0 = __ldg(fp);
    float4 v1 = __ldg(fp + 8);
    float4 v2 = __ldg(fp + 16);
    asm volatile("red.global.add.v4.f32 [%0], {%1,%2,%3,%4};"
                 :: "l"(pp), "f"(v0.x), "f"(v0.y), "f"(v0.z), "f"(v0.w) : "memory");
    asm volatile("red.global.add.v4.f32 [%0], {%1,%2,%3,%4};"
                 :: "l"(pp + 8), "f"(v1.x), "f"(v1.y), "f"(v1.z), "f"(v1.w) : "memory");
    asm volatile("red.global.add.v4.f32 [%0], {%1,%2,%3,%4};"
                 :: "l"(pp + 16), "f"(v2.x), "f"(v2.y), "f"(v2.z), "f"(v2.w) : "memory");
}

// ---------------- K3: fused  h2 = relu((pool+s*feat)@W1+b1)@W2+b2 + stats ---
#define TM 128
#define AS 100   // padded row stride for A tile

__global__ __launch_bounds__(256, 2)
void mlp_kernel(const float4* __restrict__ feat,
                const float* __restrict__ eps,
                const float* __restrict__ W1, const float* __restrict__ b1,
                const float* __restrict__ W2, const float* __restrict__ b2,
                float* __restrict__ out, int n) {
    extern __shared__ float smem[];
    float* As    = smem;                 // TM * AS
    float* Ws    = smem + TM * AS;       // 96*96
    float* s_sum = Ws + D * D;           // 96
    float* s_sq  = s_sum + D;            // 96

    const int tid = threadIdx.x;
    const int tx  = tid & 7;
    const int ty  = tid >> 3;
    const int rb  = blockIdx.x * TM;

    if (tid < D) { s_sum[tid] = 0.f; s_sq[tid] = 0.f; }

    const float se = 1.0f + __ldg(eps);
    for (int i = tid; i < TM * D4; i += 256) {
        int r  = i / D4;
        int c4 = i - r * D4;
        float4 v = make_float4(0.f, 0.f, 0.f, 0.f);
        if (rb + r < n) {
            long idx = (long)(rb + r) * D4 + c4;
            float4 p = g_pool[idx];
            float4 f = __ldg(feat + idx);
            v.x = fmaf(se, f.x, p.x);
            v.y = fmaf(se, f.y, p.y);
            v.z = fmaf(se, f.z, p.z);
            v.w = fmaf(se, f.w, p.w);
        }
        *(float4*)(As + r * AS + c4 * 4) = v;
    }
    for (int i = tid; i < (D * D) / 4; i += 256)
        ((float4*)Ws)[i] = ((const float4*)W1)[i];
    __syncthreads();

    float acc[4][12];
    #pragma unroll
    for (int r = 0; r < 4; r++)
        #pragma unroll
        for (int c = 0; c < 12; c++) acc[r][c] = 0.f;

    // ---- GEMM1 ----
    #pragma unroll 6
    for (int k4 = 0; k4 < D; k4 += 4) {
        float4 av[4];
        #pragma unroll
        for (int r = 0; r < 4; r++)
            av[r] = *(const float4*)(As + (ty * 4 + r) * AS + k4);
        #pragma unroll
        for (int kk = 0; kk < 4; kk++) {
            int k = k4 + kk;
            float4 w0 = *(const float4*)(Ws + k * D + tx * 12);
            float4 w1 = *(const float4*)(Ws + k * D + tx * 12 + 4);
            float4 w2 = *(const float4*)(Ws + k * D + tx * 12 + 8);
            float wv[12] = {w0.x,w0.y,w0.z,w0.w, w1.x,w1.y,w1.z,w1.w,
                            w2.x,w2.y,w2.z,w2.w};
            #pragma unroll
            for (int r = 0; r < 4; r++) {
                float a = (kk == 0) ? av[r].x : (kk == 1) ? av[r].y
                        : (kk == 2) ? av[r].z : av[r].w;
                #pragma unroll
                for (int c = 0; c < 12; c++)
                    acc[r][c] = fmaf(a, wv[c], acc[r][c]);
            }
        }
    }
    __syncthreads();

    #pragma unroll
    for (int c = 0; c < 12; c++) {
        float bb = __ldg(b1 + tx * 12 + c);
        #pragma unroll
        for (int r = 0; r < 4; r++)
            As[(ty * 4 + r) * AS + tx * 12 + c] = fmaxf(acc[r][c] + bb, 0.f);
    }
    for (int i = tid; i < (D * D) / 4; i += 256)
        ((float4*)Ws)[i] = ((const float4*)W2)[i];
    __syncthreads();

    #pragma unroll
    for (int r = 0; r < 4; r++)
        #pragma unroll
        for (int c = 0; c < 12; c++) acc[r][c] = 0.f;

    // ---- GEMM2 ----
    #pragma unroll 6
    for (int k4 = 0; k4 < D; k4 += 4) {
        float4 av[4];
        #pragma unroll
        for (int r = 0; r < 4; r++)
            av[r] = *(const float4*)(As + (ty * 4 + r) * AS + k4);
        #pragma unroll
        for (int kk = 0; kk < 4; kk++) {
            int k = k4 + kk;
            float4 w0 = *(const float4*)(Ws + k * D + tx * 12);
            float4 w1 = *(const float4*)(Ws + k * D + tx * 12 + 4);
            float4 w2 = *(const float4*)(Ws + k * D + tx * 12 + 8);
            float wv[12] = {w0.x,w0.y,w0.z,w0.w, w1.x,w1.y,w1.z,w1.w,
                            w2.x,w2.y,w2.z,w2.w};
            #pragma unroll
            for (int r = 0; r < 4; r++) {
                float a = (kk == 0) ? av[r].x : (kk == 1) ? av[r].y
                        : (kk == 2) ? av[r].z : av[r].w;
                #pragma unroll
                for (int c = 0; c < 12; c++)
                    acc[r][c] = fmaf(a, wv[c], acc[r][c]);
            }
        }
    }

    // ---- epilogue: +b2, store h2, reduce BN sums ----
    #pragma unroll
    for (int c = 0; c < 12; c++) {
        int col = tx * 12 + c;
        float bb = __ldg(b2 + col);
        float s = 0.f, s2 = 0.f;
        #pragma unroll
        for (int r = 0; r < 4; r++) {
            int row = rb + ty * 4 + r;
            float v = acc[r][c] + bb;
            if (row < n) {
                out[row * D + col] = v;
                s  += v;
                s2 += v * v;
            }
        }
        s  += __shfl_xor_sync(0xffffffffu, s, 8);
        s  += __shfl_xor_sync(0xffffffffu, s, 16);
        s2 += __shfl_xor_sync(0xffffffffu, s2, 8);
        s2 += __shfl_xor_sync(0xffffffffu, s2, 16);
        if ((tid & 31) < 8) {
            atomicAdd(&s_sum[col], s);
            atomicAdd(&s_sq[col], s2);
        }
    }
    __syncthreads();
    if (tid < D) {
        atomicAdd(&g_sum[tid],   s_sum[tid]);
        atomicAdd(&g_sumsq[tid], s_sq[tid]);
    }
}

// ---------------- K4: apply BN + ReLU, 1 float4 per thread -------------------
__global__ void apply_kernel(const float* __restrict__ gamma,
                             const float* __restrict__ beta,
                             float invN, float4* __restrict__ out4, int n4) {
    __shared__ __align__(16) float sc[D];
    __shared__ __align__(16) float sh[D];
    int tid = threadIdx.x;
    if (tid < D) {
        float mean = g_sum[tid] * invN;
        float var  = g_sumsq[tid] * invN - mean * mean;
        float rstd = rsqrtf(var + 1e-5f);
        float s    = rstd * gamma[tid];
        sc[tid] = s;
        sh[tid] = beta[tid] - mean * s;
    }
    __syncthreads();

    int i = blockIdx.x * blockDim.x + tid;
    if (i >= n4) return;
    int c4 = i % D4;
    float4 h  = out4[i];
    float4 s4 = ((const float4*)sc)[c4];
    float4 h4 = ((const float4*)sh)[c4];
    h.x = fmaxf(fmaf(h.x, s4.x, h4.x), 0.f);
    h.y = fmaxf(fmaf(h.y, s4.y, h4.y), 0.f);
    h.z = fmaxf(fmaf(h.z, s4.z, h4.z), 0.f);
    h.w = fmaxf(fmaf(h.w, s4.w, h4.w), 0.f);
    out4[i] = h;
}

// ---------------------------------------------------------------------------
extern "C" void kernel_launch(void* const* d_in, const int* in_sizes, int n_in,
                              void* d_out, int out_size) {
    const float* feature = (const float*)d_in[0];
    const int*   src     = (const int*)d_in[1];
    const int*   dst     = (const int*)d_in[2];
    const float* W1      = (const float*)d_in[3];
    const float* b1      = (const float*)d_in[4];
    const float* W2      = (const float*)d_in[5];
    const float* b2      = (const float*)d_in[6];
    const float* gamma   = (const float*)d_in[7];
    const float* beta    = (const float*)d_in[8];
    const float* eps     = (const float*)d_in[9];
    float* out = (float*)d_out;

    const int n  = in_sizes[0] / D;     // 50000
    const int E  = in_sizes[1];         // 800000
    const int n4 = n * D4;

    zero_kernel<<<(n4 + 255) / 256, 256>>>(n4);

    int total = E * 8;                   // 6.4M threads, 3 chunks each
    scatter_kernel<<<(total + 255) / 256, 256>>>((const float4*)feature,
                                                 src, dst, total);

    const int SMEM = (TM * AS + D * D + 2 * D) * (int)sizeof(float); // 88832 B
    cudaFuncSetAttribute(mlp_kernel,
                         cudaFuncAttributeMaxDynamicSharedMemorySize, SMEM);
    mlp_kernel<<<(n + TM - 1) / TM, 256, SMEM>>>((const float4*)feature, eps,
                                                 W1, b1, W2, b2, out, n);

    apply_kernel<<<(n4 + 255) / 256, 256>>>(gamma, beta, 1.0f / (float)n,
                                            (float4*)out, n4);
}

// round 8
// speedup vs baseline: 1.2410x; 1.2238x over previous
#include <cuda_runtime.h>
#include <cuda_bf16.h>

#define NMAX   50000
#define D      96
#define D4     24
#define TM     128
#define STRA   104    // A tile row stride (bf16 elems) -> conflict-free frags
#define STRW   104    // Wt tile row stride

typedef unsigned int  u32;
typedef unsigned short ushort_t;

// ---------------- scratch (device globals; no allocation allowed) ----------
__device__ float4 g_pool[NMAX * D4];            // pooled neighbor sums (19.2 MB)
__device__ float  g_sum[D];
__device__ float  g_sumsq[D];

// ---------------- K1: zero pool + BN accumulators ---------------------------
__global__ void zero_kernel(int n4) {
    int i = blockIdx.x * blockDim.x + threadIdx.x;
    if (i < D) { g_sum[i] = 0.f; g_sumsq[i] = 0.f; }
    if (i >= n4) return;
    g_pool[i] = make_float4(0.f, 0.f, 0.f, 0.f);
}

// ---------------- K2: edge scatter: pool[dst] += feature[src] ---------------
__global__ void scatter_kernel(const float4* __restrict__ feat,
                               const int* __restrict__ src,
                               const int* __restrict__ dst, int total) {
    int i = blockIdx.x * blockDim.x + threadIdx.x;
    if (i >= total) return;
    int e = i >> 3;
    int j = i & 7;
    int s = __ldg(src + e);
    int d = __ldg(dst + e);
    const float4* fp = feat + (long)s * D4 + j;
    float4* pp = g_pool + (long)d * D4 + j;
    float4 v0 = __ldg(fp);
    float4 v1 = __ldg(fp + 8);
    float4 v2 = __ldg(fp + 16);
    asm volatile("red.global.add.v4.f32 [%0], {%1,%2,%3,%4};"
                 :: "l"(pp), "f"(v0.x), "f"(v0.y), "f"(v0.z), "f"(v0.w) : "memory");
    asm volatile("red.global.add.v4.f32 [%0], {%1,%2,%3,%4};"
                 :: "l"(pp + 8), "f"(v1.x), "f"(v1.y), "f"(v1.z), "f"(v1.w) : "memory");
    asm volatile("red.global.add.v4.f32 [%0], {%1,%2,%3,%4};"
                 :: "l"(pp + 16), "f"(v2.x), "f"(v2.y), "f"(v2.z), "f"(v2.w) : "memory");
}

// ---------------- K3: tensor-core MLP + BN stats -----------------------------
#define MMA_BF16(c, a0, a1, a2, a3, b0, b1) \
    asm volatile("mma.sync.aligned.m16n8k16.row.col.f32.bf16.bf16.f32 " \
                 "{%0,%1,%2,%3}, {%4,%5,%6,%7}, {%8,%9}, {%0,%1,%2,%3};" \
                 : "+f"((c)[0]), "+f"((c)[1]), "+f"((c)[2]), "+f"((c)[3]) \
                 : "r"(a0), "r"(a1), "r"(a2), "r"(a3), "r"(b0), "r"(b1))

__device__ __forceinline__ void split_store(ushort_t* hi, ushort_t* lo,
                                            float v0, float v1) {
    __nv_bfloat162 h = __float22bfloat162_rn(make_float2(v0, v1));
    float2 rf = make_float2(v0 - __bfloat162float(h.x),
                            v1 - __bfloat162float(h.y));
    __nv_bfloat162 l = __float22bfloat162_rn(rf);
    *(u32*)hi = *(u32*)&h;
    *(u32*)lo = *(u32*)&l;
}

__device__ __forceinline__ void do_gemm(const ushort_t* __restrict__ Ahi,
                                        const ushort_t* __restrict__ Alo,
                                        const ushort_t* __restrict__ Whi,
                                        const ushort_t* __restrict__ Wlo,
                                        float c[12][4], int ar0, int tq, int g) {
    for (int kt = 0; kt < 6; kt++) {
        int kc = kt * 16 + tq * 2;
        const ushort_t* pah = Ahi + ar0 * STRA + kc;
        const ushort_t* pal = Alo + ar0 * STRA + kc;
        u32 ah0 = *(const u32*)(pah);
        u32 ah1 = *(const u32*)(pah + 8 * STRA);
        u32 ah2 = *(const u32*)(pah + 8);
        u32 ah3 = *(const u32*)(pah + 8 * STRA + 8);
        u32 al0 = *(const u32*)(pal);
        u32 al1 = *(const u32*)(pal + 8 * STRA);
        u32 al2 = *(const u32*)(pal + 8);
        u32 al3 = *(const u32*)(pal + 8 * STRA + 8);
        #pragma unroll
        for (int nt = 0; nt < 12; nt++) {
            const ushort_t* pbh = Whi + (nt * 8 + g) * STRW + kc;
            const ushort_t* pbl = Wlo + (nt * 8 + g) * STRW + kc;
            u32 bh0 = *(const u32*)(pbh);
            u32 bh1 = *(const u32*)(pbh + 8);
            u32 bl0 = *(const u32*)(pbl);
            u32 bl1 = *(const u32*)(pbl + 8);
            MMA_BF16(c[nt], ah0, ah1, ah2, ah3, bh0, bh1);
            MMA_BF16(c[nt], ah0, ah1, ah2, ah3, bl0, bl1);
            MMA_BF16(c[nt], al0, al1, al2, al3, bh0, bh1);
        }
    }
}

#define A_ELEMS (TM * STRA)   // 13312
#define W_ELEMS (D * STRW)    // 9984

__global__ __launch_bounds__(256, 2)
void mlp_kernel(const float4* __restrict__ feat,
                const float* __restrict__ eps,
                const float* __restrict__ W1, const float* __restrict__ b1,
                const float* __restrict__ W2, const float* __restrict__ b2,
                float* __restrict__ out, int n) {
    extern __shared__ ushort_t smem[];
    ushort_t* Ahi = smem;
    ushort_t* Alo = Ahi + A_ELEMS;
    ushort_t* Whi = Alo + A_ELEMS;
    ushort_t* Wlo = Whi + W_ELEMS;
    float* s_sum = (float*)(Wlo + W_ELEMS);   // 93184B offset, 4B aligned
    float* s_sq  = s_sum + D;

    const int tid  = threadIdx.x;
    const int lane = tid & 31;
    const int warp = tid >> 5;           // 0..7, warp owns rows [warp*16, +16)
    const int tq   = lane & 3;
    const int g    = lane >> 2;          // 0..7
    const int rb   = blockIdx.x * TM;
    const int ar0  = warp * 16 + g;      // block-local A row for a0/a2

    if (tid < D) { s_sum[tid] = 0.f; s_sq[tid] = 0.f; }

    // ---- stage A = pool + (1+eps)*feat, bf16 split ----
    const float se = 1.0f + __ldg(eps);
    for (int i = tid; i < TM * D4; i += 256) {
        int r  = i / D4;
        int c4 = i - r * D4;
        float4 v = make_float4(0.f, 0.f, 0.f, 0.f);
        if (rb + r < n) {
            long idx = (long)(rb + r) * D4 + c4;
            float4 p = g_pool[idx];
            float4 f = __ldg(feat + idx);
            v.x = fmaf(se, f.x, p.x);
            v.y = fmaf(se, f.y, p.y);
            v.z = fmaf(se, f.z, p.z);
            v.w = fmaf(se, f.w, p.w);
        }
        int off = r * STRA + c4 * 4;
        split_store(Ahi + off,     Alo + off,     v.x, v.y);
        split_store(Ahi + off + 2, Alo + off + 2, v.z, v.w);
    }
    // ---- stage W1 transposed (Wt[n][k]), bf16 split ----
    for (int i = tid; i < D * D; i += 256) {
        int k  = i / D;
        int nn = i - k * D;
        float wv = __ldg(W1 + i);
        __nv_bfloat16 h = __float2bfloat16(wv);
        Whi[nn * STRW + k] = __bfloat16_as_ushort(h);
        Wlo[nn * STRW + k] =
            __bfloat16_as_ushort(__float2bfloat16(wv - __bfloat162float(h)));
    }
    __syncthreads();

    float c[12][4];
    #pragma unroll
    for (int nt = 0; nt < 12; nt++)
        #pragma unroll
        for (int q = 0; q < 4; q++) c[nt][q] = 0.f;

    // ---- GEMM1 ----
    do_gemm(Ahi, Alo, Whi, Wlo, c, ar0, tq, g);
    __syncthreads();   // all warps done reading A, W1t

    // ---- h1 = relu(c + b1) -> split back into A tiles (warp-private rows) ---
    #pragma unroll
    for (int nt = 0; nt < 12; nt++) {
        int n0 = nt * 8 + tq * 2;
        float bb0 = __ldg(b1 + n0);
        float bb1 = __ldg(b1 + n0 + 1);
        float v00 = fmaxf(c[nt][0] + bb0, 0.f);
        float v01 = fmaxf(c[nt][1] + bb1, 0.f);
        float v10 = fmaxf(c[nt][2] + bb0, 0.f);
        float v11 = fmaxf(c[nt][3] + bb1, 0.f);
        int r0 = (warp * 16 + g) * STRA + n0;
        int r1 = r0 + 8 * STRA;
        split_store(Ahi + r0, Alo + r0, v00, v01);
        split_store(Ahi + r1, Alo + r1, v10, v11);
    }
    // ---- stage W2 transposed ----
    for (int i = tid; i < D * D; i += 256) {
        int k  = i / D;
        int nn = i - k * D;
        float wv = __ldg(W2 + i);
        __nv_bfloat16 h = __float2bfloat16(wv);
        Whi[nn * STRW + k] = __bfloat16_as_ushort(h);
        Wlo[nn * STRW + k] =
            __bfloat16_as_ushort(__float2bfloat16(wv - __bfloat162float(h)));
    }
    __syncthreads();

    #pragma unroll
    for (int nt = 0; nt < 12; nt++)
        #pragma unroll
        for (int q = 0; q < 4; q++) c[nt][q] = 0.f;

    // ---- GEMM2 ----
    do_gemm(Ahi, Alo, Whi, Wlo, c, ar0, tq, g);

    // ---- epilogue: +b2, store h2, BN sums ----
    #pragma unroll
    for (int nt = 0; nt < 12; nt++) {
        int n0 = nt * 8 + tq * 2;
        float bb0 = __ldg(b2 + n0);
        float bb1 = __ldg(b2 + n0 + 1);
        int row0 = rb + warp * 16 + g;
        int row1 = row0 + 8;
        float v00 = c[nt][0] + bb0;
        float v01 = c[nt][1] + bb1;
        float v10 = c[nt][2] + bb0;
        float v11 = c[nt][3] + bb1;
        float s0 = 0.f, s1 = 0.f, q0 = 0.f, q1 = 0.f;
        if (row0 < n) {
            *(float2*)(out + (long)row0 * D + n0) = make_float2(v00, v01);
            s0 += v00; s1 += v01; q0 += v00 * v00; q1 += v01 * v01;
        }
        if (row1 < n) {
            *(float2*)(out + (long)row1 * D + n0) = make_float2(v10, v11);
            s0 += v10; s1 += v11; q0 += v10 * v10; q1 += v11 * v11;
        }
        #pragma unroll
        for (int m = 4; m < 32; m <<= 1) {
            s0 += __shfl_xor_sync(0xffffffffu, s0, m);
            s1 += __shfl_xor_sync(0xffffffffu, s1, m);
            q0 += __shfl_xor_sync(0xffffffffu, q0, m);
            q1 += __shfl_xor_sync(0xffffffffu, q1, m);
        }
        if (g == 0) {
            atomicAdd(&s_sum[n0],     s0);
            atomicAdd(&s_sum[n0 + 1], s1);
            atomicAdd(&s_sq[n0],      q0);
            atomicAdd(&s_sq[n0 + 1],  q1);
        }
    }
    __syncthreads();
    if (tid < D) {
        atomicAdd(&g_sum[tid],   s_sum[tid]);
        atomicAdd(&g_sumsq[tid], s_sq[tid]);
    }
}

// ---------------- K4: apply BN + ReLU, 1 float4 per thread -------------------
__global__ void apply_kernel(const float* __restrict__ gamma,
                             const float* __restrict__ beta,
                             float invN, float4* __restrict__ out4, int n4) {
    __shared__ __align__(16) float sc[D];
    __shared__ __align__(16) float sh[D];
    int tid = threadIdx.x;
    if (tid < D) {
        float mean = g_sum[tid] * invN;
        float var  = g_sumsq[tid] * invN - mean * mean;
        float rstd = rsqrtf(var + 1e-5f);
        float s    = rstd * gamma[tid];
        sc[tid] = s;
        sh[tid] = beta[tid] - mean * s;
    }
    __syncthreads();

    int i = blockIdx.x * blockDim.x + tid;
    if (i >= n4) return;
    int c4 = i % D4;
    float4 h  = out4[i];
    float4 s4 = ((const float4*)sc)[c4];
    float4 h4 = ((const float4*)sh)[c4];
    h.x = fmaxf(fmaf(h.x, s4.x, h4.x), 0.f);
    h.y = fmaxf(fmaf(h.y, s4.y, h4.y), 0.f);
    h.z = fmaxf(fmaf(h.z, s4.z, h4.z), 0.f);
    h.w = fmaxf(fmaf(h.w, s4.w, h4.w), 0.f);
    out4[i] = h;
}

// ---------------------------------------------------------------------------
extern "C" void kernel_launch(void* const* d_in, const int* in_sizes, int n_in,
                              void* d_out, int out_size) {
    const float* feature = (const float*)d_in[0];
    const int*   src     = (const int*)d_in[1];
    const int*   dst     = (const int*)d_in[2];
    const float* W1      = (const float*)d_in[3];
    const float* b1      = (const float*)d_in[4];
    const float* W2      = (const float*)d_in[5];
    const float* b2      = (const float*)d_in[6];
    const float* gamma   = (const float*)d_in[7];
    const float* beta    = (const float*)d_in[8];
    const float* eps     = (const float*)d_in[9];
    float* out = (float*)d_out;

    const int n  = in_sizes[0] / D;     // 50000
    const int E  = in_sizes[1];         // 800000
    const int n4 = n * D4;

    zero_kernel<<<(n4 + 255) / 256, 256>>>(n4);

    int total = E * 8;
    scatter_kernel<<<(total + 255) / 256, 256>>>((const float4*)feature,
                                                 src, dst, total);

    const int SMEM = (2 * A_ELEMS + 2 * W_ELEMS) * 2 + 2 * D * 4; // 93952 B
    cudaFuncSetAttribute(mlp_kernel,
                         cudaFuncAttributeMaxDynamicSharedMemorySize, SMEM);
    mlp_kernel<<<(n + TM - 1) / TM, 256, SMEM>>>((const float4*)feature, eps,
                                                 W1, b1, W2, b2, out, n);

    apply_kernel<<<(n4 + 255) / 256, 256>>>(gamma, beta, 1.0f / (float)n,
                                            (float4*)out, n4);
}